// round 3
// baseline (speedup 1.0000x reference)
#include <cuda_runtime.h>
#include <math.h>

#define N       512
#define NN      (512*512)
#define NBATCH  64
#define NCH     3
#define HW      NN
#define HW4     (HW/4)
#define KSPLIT  4
#define BT      8            // batches per group in main pass

#define BM 128
#define BN 128
#define BK 16

// ---- device scratch (allocation-free: static globals) ----
__device__ float g_D[NN];                 // DCT-II matrix [k][n]
__device__ float g_T[NN];                 // D^T @ att
__device__ float g_Q[NN];                 // att @ D
__device__ float g_Wrow[NN];
__device__ float g_Wcol[NN];
__device__ float g_part[2 * KSPLIT * NN]; // k-split partials for 2 concurrent GEMMs
__device__ float g_acc[NBATCH * 2];       // [b][{col,row}]

// ---- packed f32x2 helpers (Blackwell FFMA2: 2 FMA / instr) ----
__device__ __forceinline__ void fma2(unsigned long long &c, unsigned long long a,
                                     unsigned long long b) {
    asm("fma.rn.f32x2 %0, %1, %2, %0;" : "+l"(c) : "l"(a), "l"(b));
}
__device__ __forceinline__ unsigned long long pk2(float lo, float hi) {
    unsigned long long r;
    asm("mov.b64 %0, {%1, %2};" : "=l"(r) : "f"(lo), "f"(hi));
    return r;
}
__device__ __forceinline__ void upk2(unsigned long long v, float &lo, float &hi) {
    asm("mov.b64 {%0, %1}, %2;" : "=f"(lo), "=f"(hi) : "l"(v));
}

// ---- K0: build DCT matrix (exact integer angle reduction) + zero accumulators ----
__global__ void k_init() {
    int idx = blockIdx.x * blockDim.x + threadIdx.x;
    if (idx < NN) {
        int k = idx >> 9;          // row (frequency)
        int n = idx & 511;         // col (spatial)
        // angle = pi*(n+0.5)*k/N = pi * ((2n+1)k) / (2N); period 2pi -> mod 4N=2048
        int m = ((2 * n + 1) * k) & 2047;
        float ang = (float)m * 3.06796157577e-3f;  // pi/1024
        float c = cosf(ang);
        float s = (k == 0) ? 0.04419417382415922f  // sqrt(1/512)
                           : 0.0625f;              // sqrt(2/512)
        g_D[idx] = s * c;
    }
    if (idx < NBATCH * 2) g_acc[idx] = 0.0f;
}

// ---- GEMM stage: two independent 512^3 GEMMs fused into one grid, K-split 4 ----
// C[i,j] = sum_p opA(p,i) * sA[p] * B[p,j] * sB[p]
//   transA=1: opA = A[p*N+i] ; transA=0: opA = A[i*N+p]
// Output goes to per-ksplit partial buffer (no atomics, no pre-zero).
__global__ void __launch_bounds__(256) k_stage(int stage, const float* __restrict__ att,
                                               const float* __restrict__ rw,
                                               const float* __restrict__ cw) {
    const int g  = blockIdx.z & 1;
    const int kz = blockIdx.z >> 1;

    const float *A, *B, *sA = nullptr, *sB = nullptr;
    float* P;
    int transA;
    if (stage == 0) {
        if (g == 0) { A = g_D; B = att; transA = 1; P = g_part; }               // T = D^T att
        else        { A = att; B = g_D; transA = 0; P = g_part + KSPLIT * NN; } // Q = att D
    } else {
        if (g == 0) { A = g_D; B = g_Q; transA = 1; sA = rw; P = g_part; }      // Wrow
        else        { A = g_T; B = g_D; transA = 0; sB = cw; P = g_part + KSPLIT * NN; } // Wcol
    }
    P += kz * NN;

    __shared__ float As[BK][BM + 4];
    __shared__ float Bs[BK][BN + 4];

    const int t  = threadIdx.x;
    const int tx = t & 15;
    const int ty = t >> 4;
    const int i0 = blockIdx.y * BM;
    const int j0 = blockIdx.x * BN;
    const int kbase = kz * (N / KSPLIT);   // 128-wide K chunk

    unsigned long long c2[8][4];
#pragma unroll
    for (int ii = 0; ii < 8; ii++)
#pragma unroll
        for (int jj = 0; jj < 4; jj++) c2[ii][jj] = pk2(0.f, 0.f);

    for (int kt = 0; kt < N / KSPLIT; kt += BK) {
        const int kb = kbase + kt;
        // load A tile -> As[p][i]
        if (transA) {
#pragma unroll
            for (int r = 0; r < 2; r++) {
                int lin = t + r * 256;
                int p = lin >> 5;
                int i4 = (lin & 31) << 2;
                float4 v = *(const float4*)(A + (size_t)(kb + p) * N + i0 + i4);
                float sc = sA ? sA[kb + p] : 1.0f;
                As[p][i4 + 0] = v.x * sc;
                As[p][i4 + 1] = v.y * sc;
                As[p][i4 + 2] = v.z * sc;
                As[p][i4 + 3] = v.w * sc;
            }
        } else {
#pragma unroll
            for (int r = 0; r < 2; r++) {
                int lin = t + r * 256;
                int i = lin >> 2;
                int p4 = (lin & 3) << 2;
                float4 v = *(const float4*)(A + (size_t)(i0 + i) * N + kb + p4);
                float s0 = sA ? sA[kb + p4 + 0] : 1.0f;
                float s1 = sA ? sA[kb + p4 + 1] : 1.0f;
                float s2 = sA ? sA[kb + p4 + 2] : 1.0f;
                float s3 = sA ? sA[kb + p4 + 3] : 1.0f;
                As[p4 + 0][i] = v.x * s0;
                As[p4 + 1][i] = v.y * s1;
                As[p4 + 2][i] = v.z * s2;
                As[p4 + 3][i] = v.w * s3;
            }
        }
        // load B tile -> Bs[p][j]
#pragma unroll
        for (int r = 0; r < 2; r++) {
            int lin = t + r * 256;
            int p = lin >> 5;
            int j4 = (lin & 31) << 2;
            float4 v = *(const float4*)(B + (size_t)(kb + p) * N + j0 + j4);
            float sc = sB ? sB[kb + p] : 1.0f;
            Bs[p][j4 + 0] = v.x * sc;
            Bs[p][j4 + 1] = v.y * sc;
            Bs[p][j4 + 2] = v.z * sc;
            Bs[p][j4 + 3] = v.w * sc;
        }
        __syncthreads();

#pragma unroll
        for (int k = 0; k < BK; k++) {
            float4 a0 = *(float4*)&As[k][ty * 8];
            float4 a1 = *(float4*)&As[k][ty * 8 + 4];
            float4 b0 = *(float4*)&Bs[k][tx * 8];
            float4 b1 = *(float4*)&Bs[k][tx * 8 + 4];
            unsigned long long bp[4] = {pk2(b0.x, b0.y), pk2(b0.z, b0.w),
                                        pk2(b1.x, b1.y), pk2(b1.z, b1.w)};
            float av[8] = {a0.x, a0.y, a0.z, a0.w, a1.x, a1.y, a1.z, a1.w};
#pragma unroll
            for (int ii = 0; ii < 8; ii++) {
                unsigned long long a2 = pk2(av[ii], av[ii]);
#pragma unroll
                for (int jj = 0; jj < 4; jj++) fma2(c2[ii][jj], a2, bp[jj]);
            }
        }
        __syncthreads();
    }

    // epilogue: plain stores into this ksplit's partial buffer
#pragma unroll
    for (int ii = 0; ii < 8; ii++) {
        int row = i0 + ty * 8 + ii;
        float4 o0, o1;
        upk2(c2[ii][0], o0.x, o0.y);
        upk2(c2[ii][1], o0.z, o0.w);
        upk2(c2[ii][2], o1.x, o1.y);
        upk2(c2[ii][3], o1.z, o1.w);
        *(float4*)(P + (size_t)row * N + j0 + tx * 8)     = o0;
        *(float4*)(P + (size_t)row * N + j0 + tx * 8 + 4) = o1;
    }
}

// ---- combine 4 k-split partials into final matrices ----
__global__ void k_combine(int stage) {
    int idx = blockIdx.x * blockDim.x + threadIdx.x;    // float4 index over NN/4
    int which = blockIdx.y;
    const float4* p = (const float4*)(g_part + (size_t)which * (KSPLIT * NN));
    float4* dst;
    if (stage == 0) dst = (float4*)(which ? g_Q : g_T);
    else            dst = (float4*)(which ? g_Wcol : g_Wrow);
    const int nn4 = NN / 4;
    float4 a = p[idx], b = p[idx + nn4], c = p[idx + 2 * nn4], d = p[idx + 3 * nn4];
    float4 o;
    o.x = a.x + b.x + c.x + d.x;
    o.y = a.y + b.y + c.y + d.y;
    o.z = a.z + b.z + c.z + d.z;
    o.w = a.w + b.w + c.w + d.w;
    dst[idx] = o;
}

// ---- main pass: stream x once, dot with Wrow/Wcol per batch ----
__global__ void __launch_bounds__(256) k_main(const float* __restrict__ x) {
    const int b0 = blockIdx.y * BT;
    const float4* __restrict__ x4  = (const float4*)x;
    const float4* __restrict__ wr4 = (const float4*)g_Wrow;
    const float4* __restrict__ wc4 = (const float4*)g_Wcol;

    float accR[BT], accC[BT];
#pragma unroll
    for (int bb = 0; bb < BT; bb++) { accR[bb] = 0.f; accC[bb] = 0.f; }

    const int stride = gridDim.x * blockDim.x;
    for (int s = blockIdx.x * blockDim.x + threadIdx.x; s < HW4; s += stride) {
        float4 wr = wr4[s];
        float4 wc = wc4[s];
#pragma unroll
        for (int bb = 0; bb < BT; bb++) {
            const float4* xb = x4 + (size_t)(b0 + bb) * NCH * HW4 + s;
            float4 p = xb[0];
            float4 q = xb[HW4];
            float4 r = xb[2 * HW4];
            float gx = p.x + q.x + r.x;
            float gy = p.y + q.y + r.y;
            float gz = p.z + q.z + r.z;
            float gw = p.w + q.w + r.w;
            accR[bb] += gx * wr.x + gy * wr.y + gz * wr.z + gw * wr.w;
            accC[bb] += gx * wc.x + gy * wc.y + gz * wc.z + gw * wc.w;
        }
    }

    // reduce: warp shuffle, then cross-warp via smem, then 16 atomics/block
#pragma unroll
    for (int bb = 0; bb < BT; bb++) {
#pragma unroll
        for (int o = 16; o > 0; o >>= 1) {
            accR[bb] += __shfl_down_sync(0xffffffffu, accR[bb], o);
            accC[bb] += __shfl_down_sync(0xffffffffu, accC[bb], o);
        }
    }
    __shared__ float sred[8][2 * BT];
    int warp = threadIdx.x >> 5, lane = threadIdx.x & 31;
    if (lane == 0) {
#pragma unroll
        for (int bb = 0; bb < BT; bb++) {
            sred[warp][bb]      = accR[bb];
            sred[warp][BT + bb] = accC[bb];
        }
    }
    __syncthreads();
    if (threadIdx.x < 2 * BT) {
        float v = 0.f;
#pragma unroll
        for (int w = 0; w < 8; w++) v += sred[w][threadIdx.x];
        if (threadIdx.x < BT)
            atomicAdd(&g_acc[(b0 + threadIdx.x) * 2 + 1], v);        // row -> out[:,1]
        else
            atomicAdd(&g_acc[(b0 + threadIdx.x - BT) * 2 + 0], v);   // col -> out[:,0]
    }
}

// ---- final: scale + sigmoid ----
__global__ void k_final(float* __restrict__ out) {
    int i = threadIdx.x;
    if (i < NBATCH * 2) {
        float z = g_acc[i] * (1.0f / (3.0f * 512.0f * 512.0f));
        out[i] = 1.0f / (1.0f + expf(-z));
    }
}

extern "C" void kernel_launch(void* const* d_in, const int* in_sizes, int n_in,
                              void* d_out, int out_size) {
    const float* x   = (const float*)d_in[0];
    const float* att = (const float*)d_in[1];
    const float* rw  = (const float*)d_in[2];
    const float* cw  = (const float*)d_in[3];
    float* out = (float*)d_out;

    k_init<<<(NN + 255) / 256, 256>>>();
    k_stage<<<dim3(N / BN, N / BM, 2 * KSPLIT), 256>>>(0, att, rw, cw);
    k_combine<<<dim3(NN / 4 / 256, 2), 256>>>(0);
    k_stage<<<dim3(N / BN, N / BM, 2 * KSPLIT), 256>>>(1, att, rw, cw);
    k_combine<<<dim3(NN / 4 / 256, 2), 256>>>(1);
    k_main<<<dim3(48, NBATCH / BT), 256>>>(x);
    k_final<<<1, 128>>>(out);
}

// round 4
// speedup vs baseline: 1.1181x; 1.1181x over previous
#include <cuda_runtime.h>
#include <math.h>

#define N       512
#define NN      (512*512)
#define NBATCH  64
#define NCH     3
#define HW      NN
#define HW4     (HW/4)
#define KSPLIT  8
#define BT      8            // batches per group in main pass

#define BM 128
#define BN 128
#define BK 16

// ---- device scratch (allocation-free: static globals) ----
__device__ float g_D[NN];                 // DCT-II matrix [k][n]
__device__ float g_T[NN];                 // D^T @ att
__device__ float g_Q[NN];                 // att @ D
__device__ float g_Wrow[NN];
__device__ float g_Wcol[NN];
__device__ float g_part[2 * KSPLIT * NN]; // k-split partials for 2 concurrent GEMMs
__device__ float g_acc[NBATCH * 2];       // [b][{col,row}]

// ---- packed f32x2 helpers (Blackwell FFMA2: 2 FMA / instr) ----
__device__ __forceinline__ void fma2(unsigned long long &c, unsigned long long a,
                                     unsigned long long b) {
    asm("fma.rn.f32x2 %0, %1, %2, %0;" : "+l"(c) : "l"(a), "l"(b));
}
__device__ __forceinline__ unsigned long long pk2(float lo, float hi) {
    unsigned long long r;
    asm("mov.b64 %0, {%1, %2};" : "=l"(r) : "f"(lo), "f"(hi));
    return r;
}
__device__ __forceinline__ void upk2(unsigned long long v, float &lo, float &hi) {
    asm("mov.b64 {%0, %1}, %2;" : "=f"(lo), "=f"(hi) : "l"(v));
}

// ---- K0: build DCT matrix (exact integer angle reduction) + zero accumulators ----
__global__ void k_init() {
    int idx = blockIdx.x * blockDim.x + threadIdx.x;
    if (idx < NN) {
        int k = idx >> 9;          // row (frequency)
        int n = idx & 511;         // col (spatial)
        // angle = pi*(n+0.5)*k/N = pi * ((2n+1)k) / (2N); period 2pi -> mod 4N=2048
        int m = ((2 * n + 1) * k) & 2047;
        float ang = (float)m * 3.06796157577e-3f;  // pi/1024
        float c = __cosf(ang);
        float s = (k == 0) ? 0.04419417382415922f  // sqrt(1/512)
                           : 0.0625f;              // sqrt(2/512)
        g_D[idx] = s * c;
    }
    if (idx < NBATCH * 2) g_acc[idx] = 0.0f;
}

// ---- GEMM stage: two independent 512^3 GEMMs fused into one grid, K-split 8 ----
// C[i,j] = sum_p opA(p,i) * sA[p] * B[p,j] * sB[p]
//   transA=1: opA = A[p*N+i] ; transA=0: opA = A[i*N+p]
// Output goes to per-ksplit partial buffer (no atomics, no pre-zero).
__global__ void __launch_bounds__(256, 2) k_stage(int stage, const float* __restrict__ att,
                                                  const float* __restrict__ rw,
                                                  const float* __restrict__ cw) {
    const int g  = blockIdx.z & 1;
    const int kz = blockIdx.z >> 1;

    const float *A, *B, *sA = nullptr, *sB = nullptr;
    float* P;
    int transA;
    if (stage == 0) {
        if (g == 0) { A = g_D; B = att; transA = 1; P = g_part; }               // T = D^T att
        else        { A = att; B = g_D; transA = 0; P = g_part + KSPLIT * NN; } // Q = att D
    } else {
        if (g == 0) { A = g_D; B = g_Q; transA = 1; sA = rw; P = g_part; }      // Wrow
        else        { A = g_T; B = g_D; transA = 0; sB = cw; P = g_part + KSPLIT * NN; } // Wcol
    }
    P += kz * NN;

    __shared__ float As[BK][BM + 4];
    __shared__ float Bs[BK][BN + 4];

    const int t  = threadIdx.x;
    const int tx = t & 15;
    const int ty = t >> 4;
    const int i0 = blockIdx.y * BM;
    const int j0 = blockIdx.x * BN;
    const int kbase = kz * (N / KSPLIT);   // 64-wide K chunk

    unsigned long long c2[8][4];
#pragma unroll
    for (int ii = 0; ii < 8; ii++)
#pragma unroll
        for (int jj = 0; jj < 4; jj++) c2[ii][jj] = pk2(0.f, 0.f);

    for (int kt = 0; kt < N / KSPLIT; kt += BK) {
        const int kb = kbase + kt;
        // load A tile -> As[p][i]
        if (transA) {
#pragma unroll
            for (int r = 0; r < 2; r++) {
                int lin = t + r * 256;
                int p = lin >> 5;
                int i4 = (lin & 31) << 2;
                float4 v = *(const float4*)(A + (size_t)(kb + p) * N + i0 + i4);
                float sc = sA ? sA[kb + p] : 1.0f;
                As[p][i4 + 0] = v.x * sc;
                As[p][i4 + 1] = v.y * sc;
                As[p][i4 + 2] = v.z * sc;
                As[p][i4 + 3] = v.w * sc;
            }
        } else {
#pragma unroll
            for (int r = 0; r < 2; r++) {
                int lin = t + r * 256;
                int i = lin >> 2;
                int p4 = (lin & 3) << 2;
                float4 v = *(const float4*)(A + (size_t)(i0 + i) * N + kb + p4);
                float s0 = sA ? sA[kb + p4 + 0] : 1.0f;
                float s1 = sA ? sA[kb + p4 + 1] : 1.0f;
                float s2 = sA ? sA[kb + p4 + 2] : 1.0f;
                float s3 = sA ? sA[kb + p4 + 3] : 1.0f;
                As[p4 + 0][i] = v.x * s0;
                As[p4 + 1][i] = v.y * s1;
                As[p4 + 2][i] = v.z * s2;
                As[p4 + 3][i] = v.w * s3;
            }
        }
        // load B tile -> Bs[p][j]
#pragma unroll
        for (int r = 0; r < 2; r++) {
            int lin = t + r * 256;
            int p = lin >> 5;
            int j4 = (lin & 31) << 2;
            float4 v = *(const float4*)(B + (size_t)(kb + p) * N + j0 + j4);
            float sc = sB ? sB[kb + p] : 1.0f;
            Bs[p][j4 + 0] = v.x * sc;
            Bs[p][j4 + 1] = v.y * sc;
            Bs[p][j4 + 2] = v.z * sc;
            Bs[p][j4 + 3] = v.w * sc;
        }
        __syncthreads();

#pragma unroll
        for (int k = 0; k < BK; k++) {
            float4 a0 = *(float4*)&As[k][ty * 8];
            float4 a1 = *(float4*)&As[k][ty * 8 + 4];
            float4 b0 = *(float4*)&Bs[k][tx * 8];
            float4 b1 = *(float4*)&Bs[k][tx * 8 + 4];
            unsigned long long bp[4] = {pk2(b0.x, b0.y), pk2(b0.z, b0.w),
                                        pk2(b1.x, b1.y), pk2(b1.z, b1.w)};
            float av[8] = {a0.x, a0.y, a0.z, a0.w, a1.x, a1.y, a1.z, a1.w};
#pragma unroll
            for (int ii = 0; ii < 8; ii++) {
                unsigned long long a2 = pk2(av[ii], av[ii]);
#pragma unroll
                for (int jj = 0; jj < 4; jj++) fma2(c2[ii][jj], a2, bp[jj]);
            }
        }
        __syncthreads();
    }

    // epilogue: plain stores into this ksplit's partial buffer
#pragma unroll
    for (int ii = 0; ii < 8; ii++) {
        int row = i0 + ty * 8 + ii;
        float4 o0, o1;
        upk2(c2[ii][0], o0.x, o0.y);
        upk2(c2[ii][1], o0.z, o0.w);
        upk2(c2[ii][2], o1.x, o1.y);
        upk2(c2[ii][3], o1.z, o1.w);
        *(float4*)(P + (size_t)row * N + j0 + tx * 8)     = o0;
        *(float4*)(P + (size_t)row * N + j0 + tx * 8 + 4) = o1;
    }
}

// ---- combine 8 k-split partials into final matrices ----
__global__ void k_combine(int stage) {
    int idx = blockIdx.x * blockDim.x + threadIdx.x;    // float4 index over NN/4
    int which = blockIdx.y;
    const float4* p = (const float4*)(g_part + (size_t)which * (KSPLIT * NN));
    float4* dst;
    if (stage == 0) dst = (float4*)(which ? g_Q : g_T);
    else            dst = (float4*)(which ? g_Wcol : g_Wrow);
    const int nn4 = NN / 4;
    float4 o = p[idx];
#pragma unroll
    for (int i = 1; i < KSPLIT; i++) {
        float4 v = p[idx + (size_t)i * nn4];
        o.x += v.x; o.y += v.y; o.z += v.z; o.w += v.w;
    }
    dst[idx] = o;
}

// ---- main pass: stream x once, dot with Wrow/Wcol per batch ----
__global__ void __launch_bounds__(256) k_main(const float* __restrict__ x) {
    const int b0 = blockIdx.y * BT;
    const float4* __restrict__ x4  = (const float4*)x;
    const float4* __restrict__ wr4 = (const float4*)g_Wrow;
    const float4* __restrict__ wc4 = (const float4*)g_Wcol;

    float accR[BT], accC[BT];
#pragma unroll
    for (int bb = 0; bb < BT; bb++) { accR[bb] = 0.f; accC[bb] = 0.f; }

    const int stride = gridDim.x * blockDim.x;
    for (int s = blockIdx.x * blockDim.x + threadIdx.x; s < HW4; s += stride) {
        float4 wr = wr4[s];
        float4 wc = wc4[s];
#pragma unroll
        for (int bb = 0; bb < BT; bb++) {
            const float4* xb = x4 + (size_t)(b0 + bb) * NCH * HW4 + s;
            float4 p = xb[0];
            float4 q = xb[HW4];
            float4 r = xb[2 * HW4];
            float gx = p.x + q.x + r.x;
            float gy = p.y + q.y + r.y;
            float gz = p.z + q.z + r.z;
            float gw = p.w + q.w + r.w;
            accR[bb] += gx * wr.x + gy * wr.y + gz * wr.z + gw * wr.w;
            accC[bb] += gx * wc.x + gy * wc.y + gz * wc.z + gw * wc.w;
        }
    }

    // reduce: warp shuffle, then cross-warp via smem, then 16 atomics/block
#pragma unroll
    for (int bb = 0; bb < BT; bb++) {
#pragma unroll
        for (int o = 16; o > 0; o >>= 1) {
            accR[bb] += __shfl_down_sync(0xffffffffu, accR[bb], o);
            accC[bb] += __shfl_down_sync(0xffffffffu, accC[bb], o);
        }
    }
    __shared__ float sred[8][2 * BT];
    int warp = threadIdx.x >> 5, lane = threadIdx.x & 31;
    if (lane == 0) {
#pragma unroll
        for (int bb = 0; bb < BT; bb++) {
            sred[warp][bb]      = accR[bb];
            sred[warp][BT + bb] = accC[bb];
        }
    }
    __syncthreads();
    if (threadIdx.x < 2 * BT) {
        float v = 0.f;
#pragma unroll
        for (int w = 0; w < 8; w++) v += sred[w][threadIdx.x];
        if (threadIdx.x < BT)
            atomicAdd(&g_acc[(b0 + threadIdx.x) * 2 + 1], v);        // row -> out[:,1]
        else
            atomicAdd(&g_acc[(b0 + threadIdx.x - BT) * 2 + 0], v);   // col -> out[:,0]
    }
}

// ---- final: scale + sigmoid ----
__global__ void k_final(float* __restrict__ out) {
    int i = threadIdx.x;
    if (i < NBATCH * 2) {
        float z = g_acc[i] * (1.0f / (3.0f * 512.0f * 512.0f));
        out[i] = 1.0f / (1.0f + expf(-z));
    }
}

extern "C" void kernel_launch(void* const* d_in, const int* in_sizes, int n_in,
                              void* d_out, int out_size) {
    const float* x   = (const float*)d_in[0];
    const float* att = (const float*)d_in[1];
    const float* rw  = (const float*)d_in[2];
    const float* cw  = (const float*)d_in[3];
    float* out = (float*)d_out;

    k_init<<<(NN + 255) / 256, 256>>>();
    k_stage<<<dim3(N / BN, N / BM, 2 * KSPLIT), 256>>>(0, att, rw, cw);
    k_combine<<<dim3(NN / 4 / 256, 2), 256>>>(0);
    k_stage<<<dim3(N / BN, N / BM, 2 * KSPLIT), 256>>>(1, att, rw, cw);
    k_combine<<<dim3(NN / 4 / 256, 2), 256>>>(1);
    k_main<<<dim3(64, NBATCH / BT), 256>>>(x);
    k_final<<<1, 128>>>(out);
}

// round 6
// speedup vs baseline: 1.1981x; 1.0716x over previous
#include <cuda_runtime.h>
#include <math.h>

#define N       512
#define NN      (512*512)
#define NBATCH  64
#define NCH     3
#define HW      NN
#define HW4     (HW/4)
#define KSPLIT  8
#define BT      8            // batches per group in main pass

#define BM 128
#define BN 128
#define BK 16

// ---- device scratch (allocation-free: static globals) ----
__device__ float g_D[NN];                 // DCT-II matrix [k][n]
__device__ float g_T[NN];                 // D^T @ att
__device__ float g_Q[NN];                 // att @ D
__device__ float g_Wrow[NN];
__device__ float g_Wcol[NN];
__device__ float g_part[2 * KSPLIT * NN]; // k-split partials for 2 concurrent GEMMs
__device__ float g_acc[NBATCH * 2];       // [b][{col,row}]

// ---- packed f32x2 helpers (Blackwell FFMA2: 2 FMA / instr) ----
__device__ __forceinline__ void fma2(unsigned long long &c, unsigned long long a,
                                     unsigned long long b) {
    asm("fma.rn.f32x2 %0, %1, %2, %0;" : "+l"(c) : "l"(a), "l"(b));
}
__device__ __forceinline__ unsigned long long pk2(float lo, float hi) {
    unsigned long long r;
    asm("mov.b64 %0, {%1, %2};" : "=l"(r) : "f"(lo), "f"(hi));
    return r;
}
__device__ __forceinline__ void upk2(unsigned long long v, float &lo, float &hi) {
    asm("mov.b64 {%0, %1}, %2;" : "=f"(lo), "=f"(hi) : "l"(v));
}

// ---- K0: build DCT matrix (exact integer angle reduction) + zero accumulators ----
__global__ void k_init() {
    int idx = blockIdx.x * blockDim.x + threadIdx.x;
    if (idx < NN) {
        int k = idx >> 9;          // row (frequency)
        int n = idx & 511;         // col (spatial)
        // angle = pi*(n+0.5)*k/N = pi * ((2n+1)k) / (2N); period 2pi -> mod 4N=2048
        int m = ((2 * n + 1) * k) & 2047;
        float ang = (float)m * 3.06796157577e-3f;  // pi/1024
        float c = __cosf(ang);
        float s = (k == 0) ? 0.04419417382415922f  // sqrt(1/512)
                           : 0.0625f;              // sqrt(2/512)
        g_D[idx] = s * c;
    }
    if (idx < NBATCH * 2) g_acc[idx] = 0.0f;
}

// ---- GEMM stage: two independent 512^3 GEMMs fused into one grid, K-split 8 ----
// C[i,j] = sum_p opA(p,i) * sA[p] * B[p,j] * sB[p]
// Thread map: warp (0..7) owns 16 i-rows (A frag broadcast to all lanes),
//             lane (0..31) owns 4 j-cols (Bs read = contiguous 512B, N=1).
// Accumulators packed along i (f32x2 pairs direct from A float4).
__global__ void __launch_bounds__(256, 2) k_stage(int stage, const float* __restrict__ att,
                                                  const float* __restrict__ rw,
                                                  const float* __restrict__ cw) {
    const int g  = blockIdx.z & 1;
    const int kz = blockIdx.z >> 1;

    const float *A, *B, *sA = nullptr, *sB = nullptr;
    float* P;
    int transA;
    if (stage == 0) {
        if (g == 0) { A = g_D; B = att; transA = 1; P = g_part; }               // T = D^T att
        else        { A = att; B = g_D; transA = 0; P = g_part + KSPLIT * NN; } // Q = att D
    } else {
        if (g == 0) { A = g_D; B = g_Q; transA = 1; sA = rw; P = g_part; }      // Wrow
        else        { A = g_T; B = g_D; transA = 0; sB = cw; P = g_part + KSPLIT * NN; } // Wcol
    }
    P += kz * NN;

    __shared__ float As[BK][BM + 4];
    __shared__ float Bs[BK][BN + 4];

    const int t    = threadIdx.x;
    const int lane = t & 31;
    const int warp = t >> 5;
    const int i0 = blockIdx.y * BM;
    const int j0 = blockIdx.x * BN;
    const int kbase = kz * (N / KSPLIT);   // 64-wide K chunk

    unsigned long long c2[8][4];
#pragma unroll
    for (int p = 0; p < 8; p++)
#pragma unroll
        for (int jj = 0; jj < 4; jj++) c2[p][jj] = pk2(0.f, 0.f);

    for (int kt = 0; kt < N / KSPLIT; kt += BK) {
        const int kb = kbase + kt;
        // load A tile -> As[p][i]
        if (transA) {
#pragma unroll
            for (int r = 0; r < 2; r++) {
                int lin = t + r * 256;
                int p = lin >> 5;
                int i4 = (lin & 31) << 2;
                float4 v = *(const float4*)(A + (size_t)(kb + p) * N + i0 + i4);
                float sc = sA ? sA[kb + p] : 1.0f;
                As[p][i4 + 0] = v.x * sc;
                As[p][i4 + 1] = v.y * sc;
                As[p][i4 + 2] = v.z * sc;
                As[p][i4 + 3] = v.w * sc;
            }
        } else {
#pragma unroll
            for (int r = 0; r < 2; r++) {
                int lin = t + r * 256;
                int i = lin >> 2;
                int p4 = (lin & 3) << 2;
                float4 v = *(const float4*)(A + (size_t)(i0 + i) * N + kb + p4);
                float s0 = sA ? sA[kb + p4 + 0] : 1.0f;
                float s1 = sA ? sA[kb + p4 + 1] : 1.0f;
                float s2 = sA ? sA[kb + p4 + 2] : 1.0f;
                float s3 = sA ? sA[kb + p4 + 3] : 1.0f;
                As[p4 + 0][i] = v.x * s0;
                As[p4 + 1][i] = v.y * s1;
                As[p4 + 2][i] = v.z * s2;
                As[p4 + 3][i] = v.w * s3;
            }
        }
        // load B tile -> Bs[p][j]
#pragma unroll
        for (int r = 0; r < 2; r++) {
            int lin = t + r * 256;
            int p = lin >> 5;
            int j4 = (lin & 31) << 2;
            float4 v = *(const float4*)(B + (size_t)(kb + p) * N + j0 + j4);
            float sc = sB ? sB[kb + p] : 1.0f;
            Bs[p][j4 + 0] = v.x * sc;
            Bs[p][j4 + 1] = v.y * sc;
            Bs[p][j4 + 2] = v.z * sc;
            Bs[p][j4 + 3] = v.w * sc;
        }
        __syncthreads();

#pragma unroll
        for (int k = 0; k < BK; k++) {
            // A fragment: 16 i-rows for this warp, broadcast across lanes
            float4 av0 = *(const float4*)&As[k][warp * 16 + 0];
            float4 av1 = *(const float4*)&As[k][warp * 16 + 4];
            float4 av2 = *(const float4*)&As[k][warp * 16 + 8];
            float4 av3 = *(const float4*)&As[k][warp * 16 + 12];
            unsigned long long a2[8] = {
                pk2(av0.x, av0.y), pk2(av0.z, av0.w),
                pk2(av1.x, av1.y), pk2(av1.z, av1.w),
                pk2(av2.x, av2.y), pk2(av2.z, av2.w),
                pk2(av3.x, av3.y), pk2(av3.z, av3.w)};
            // B fragment: 4 j-cols for this lane, contiguous across warp (N=1)
            float4 bv = *(const float4*)&Bs[k][lane * 4];
            unsigned long long b2[4] = {pk2(bv.x, bv.x), pk2(bv.y, bv.y),
                                        pk2(bv.z, bv.z), pk2(bv.w, bv.w)};
#pragma unroll
            for (int p = 0; p < 8; p++)
#pragma unroll
                for (int jj = 0; jj < 4; jj++) fma2(c2[p][jj], a2[p], b2[jj]);
        }
        __syncthreads();
    }

    // epilogue: unpack i-pairs, store float4 per row (coalesced 512B/warp)
#pragma unroll
    for (int p = 0; p < 8; p++) {
        float4 lo4, hi4;
        upk2(c2[p][0], lo4.x, hi4.x);
        upk2(c2[p][1], lo4.y, hi4.y);
        upk2(c2[p][2], lo4.z, hi4.z);
        upk2(c2[p][3], lo4.w, hi4.w);
        int row = i0 + warp * 16 + 2 * p;
        *(float4*)(P + (size_t)row * N + j0 + lane * 4)       = lo4;
        *(float4*)(P + (size_t)(row + 1) * N + j0 + lane * 4) = hi4;
    }
}

// ---- combine 8 k-split partials into final matrices ----
__global__ void k_combine(int stage) {
    int idx = blockIdx.x * blockDim.x + threadIdx.x;    // float4 index over NN/4
    int which = blockIdx.y;
    const float4* p = (const float4*)(g_part + (size_t)which * (KSPLIT * NN));
    float4* dst;
    if (stage == 0) dst = (float4*)(which ? g_Q : g_T);
    else            dst = (float4*)(which ? g_Wcol : g_Wrow);
    const int nn4 = NN / 4;
    float4 o = p[idx];
#pragma unroll
    for (int i = 1; i < KSPLIT; i++) {
        float4 v = p[idx + (size_t)i * nn4];
        o.x += v.x; o.y += v.y; o.z += v.z; o.w += v.w;
    }
    dst[idx] = o;
}

// ---- main pass: stream x once, dot with Wrow/Wcol per batch ----
__global__ void __launch_bounds__(256) k_main(const float* __restrict__ x) {
    const int b0 = blockIdx.y * BT;
    const float4* __restrict__ x4  = (const float4*)x;
    const float4* __restrict__ wr4 = (const float4*)g_Wrow;
    const float4* __restrict__ wc4 = (const float4*)g_Wcol;

    float accR[BT], accC[BT];
#pragma unroll
    for (int bb = 0; bb < BT; bb++) { accR[bb] = 0.f; accC[bb] = 0.f; }

    const int stride = gridDim.x * blockDim.x;
    for (int s = blockIdx.x * blockDim.x + threadIdx.x; s < HW4; s += stride) {
        float4 wr = wr4[s];
        float4 wc = wc4[s];
#pragma unroll
        for (int bb = 0; bb < BT; bb++) {
            const float4* xb = x4 + (size_t)(b0 + bb) * NCH * HW4 + s;
            float4 p = xb[0];
            float4 q = xb[HW4];
            float4 r = xb[2 * HW4];
            float gx = p.x + q.x + r.x;
            float gy = p.y + q.y + r.y;
            float gz = p.z + q.z + r.z;
            float gw = p.w + q.w + r.w;
            accR[bb] += gx * wr.x + gy * wr.y + gz * wr.z + gw * wr.w;
            accC[bb] += gx * wc.x + gy * wc.y + gz * wc.z + gw * wc.w;
        }
    }

    // reduce: warp shuffle, then cross-warp via smem, then 16 atomics/block
#pragma unroll
    for (int bb = 0; bb < BT; bb++) {
#pragma unroll
        for (int o = 16; o > 0; o >>= 1) {
            accR[bb] += __shfl_down_sync(0xffffffffu, accR[bb], o);
            accC[bb] += __shfl_down_sync(0xffffffffu, accC[bb], o);
        }
    }
    __shared__ float sred[8][2 * BT];
    int warp = threadIdx.x >> 5, lane = threadIdx.x & 31;
    if (lane == 0) {
#pragma unroll
        for (int bb = 0; bb < BT; bb++) {
            sred[warp][bb]      = accR[bb];
            sred[warp][BT + bb] = accC[bb];
        }
    }
    __syncthreads();
    if (threadIdx.x < 2 * BT) {
        float v = 0.f;
#pragma unroll
        for (int w = 0; w < 8; w++) v += sred[w][threadIdx.x];
        if (threadIdx.x < BT)
            atomicAdd(&g_acc[(b0 + threadIdx.x) * 2 + 1], v);        // row -> out[:,1]
        else
            atomicAdd(&g_acc[(b0 + threadIdx.x - BT) * 2 + 0], v);   // col -> out[:,0]
    }
}

// ---- final: scale + sigmoid ----
__global__ void k_final(float* __restrict__ out) {
    int i = threadIdx.x;
    if (i < NBATCH * 2) {
        float z = g_acc[i] * (1.0f / (3.0f * 512.0f * 512.0f));
        out[i] = 1.0f / (1.0f + expf(-z));
    }
}

extern "C" void kernel_launch(void* const* d_in, const int* in_sizes, int n_in,
                              void* d_out, int out_size) {
    const float* x   = (const float*)d_in[0];
    const float* att = (const float*)d_in[1];
    const float* rw  = (const float*)d_in[2];
    const float* cw  = (const float*)d_in[3];
    float* out = (float*)d_out;

    k_init<<<(NN + 255) / 256, 256>>>();
    k_stage<<<dim3(N / BN, N / BM, 2 * KSPLIT), 256>>>(0, att, rw, cw);
    k_combine<<<dim3(NN / 4 / 256, 2), 256>>>(0);
    k_stage<<<dim3(N / BN, N / BM, 2 * KSPLIT), 256>>>(1, att, rw, cw);
    k_combine<<<dim3(NN / 4 / 256, 2), 256>>>(1);
    k_main<<<dim3(64, NBATCH / BT), 256>>>(x);
    k_final<<<1, 128>>>(out);
}